// round 16
// baseline (speedup 1.0000x reference)
#include <cuda_runtime.h>
#include <cuda_fp16.h>
#include <cstdint>

// Problem dims
#define NN   8192
#define DIN  128
#define DOUT 64

// Fused kernel layout
#define NPROD  104
#define NCONS  192
#define NGRID  (NPROD + NCONS)     // 296 = 2 x 148 (one resident wave)

// Consumer gemm tiling (R5/R14-proven skeleton, KPER = 1024)
#define M_TILE  128
#define K_TILE  64
#define SPLITK  8
#define KPER    (NN / SPLITK)      // 1024
#define NCHUNK  (KPER / K_TILE)    // 16
#define STAGES  4
#define NTILES  (SPLITK * (NN / M_TILE))   // 512

#define A_STAGE_BYTES (M_TILE * 128)            // 16 KB
#define B_STAGE_BYTES (K_TILE * 128)            // 8 KB
#define SMEM_B_BASE   (STAGES * A_STAGE_BYTES)  // 64 KB
#define SMEM_CTRL     (STAGES * (A_STAGE_BYTES + B_STAGE_BYTES))   // 96 KB
#define SMEM_TOTAL    (SMEM_CTRL + 16)          // + broadcast slot -> still 2 CTAs/SM

// Scratch (no cudaMalloc allowed; zero-initialized)
__device__ __align__(16) float  g_deg[NN];
__device__ __align__(16) __half g_ah[(size_t)NN * NN];               // fp16 copy of A
__device__ __align__(16) __half g_yh[(size_t)NN * DOUT];             // Y = d^-1/2*(X@W), fp16
__device__ __align__(16) __half g_hpart[SPLITK][(size_t)NN * DOUT];  // split-K partials (fp16)
__device__ int g_eighth[SPLITK];   // rows completed per 1024-row eighth
__device__ int g_ctask;            // consumer tile queue head

// ---------------------------------------------------------------------------
// PTX helpers (generic PTX only — harness compiles through compute_103 base)
// ---------------------------------------------------------------------------
__device__ __forceinline__ uint32_t smem_u32(const void* p) {
    uint32_t a;
    asm("{ .reg .u64 t; cvta.to.shared.u64 t, %1; cvt.u32.u64 %0, t; }" : "=r"(a) : "l"(p));
    return a;
}

#define CP_ASYNC16(dst, src) \
    asm volatile("cp.async.cg.shared.global [%0], [%1], 16;" :: "r"(dst), "l"(src) : "memory")
#define CP_COMMIT() asm volatile("cp.async.commit_group;" ::: "memory")
#define CP_WAIT2()  asm volatile("cp.async.wait_group 2;" ::: "memory")

__device__ __forceinline__ void ldsm_x4(uint32_t r[4], uint32_t addr) {
    asm volatile("ldmatrix.sync.aligned.m8n8.x4.shared.b16 {%0,%1,%2,%3}, [%4];"
                 : "=r"(r[0]), "=r"(r[1]), "=r"(r[2]), "=r"(r[3]) : "r"(addr));
}
__device__ __forceinline__ void ldsm_x4_t(uint32_t r[4], uint32_t addr) {
    asm volatile("ldmatrix.sync.aligned.m8n8.x4.trans.shared.b16 {%0,%1,%2,%3}, [%4];"
                 : "=r"(r[0]), "=r"(r[1]), "=r"(r[2]), "=r"(r[3]) : "r"(addr));
}
__device__ __forceinline__ void mma_f16(float c[4], const uint32_t a[4], uint32_t b0, uint32_t b1) {
    asm volatile(
        "mma.sync.aligned.m16n8k16.row.col.f32.f16.f16.f32 "
        "{%0,%1,%2,%3}, {%4,%5,%6,%7}, {%8,%9}, {%0,%1,%2,%3};"
        : "+f"(c[0]), "+f"(c[1]), "+f"(c[2]), "+f"(c[3])
        : "r"(a[0]), "r"(a[1]), "r"(a[2]), "r"(a[3]), "r"(b0), "r"(b1));
}

// ---------------------------------------------------------------------------
// Producer: 8-row batches — rowsum + fp16 convert + Y rows; bump eighth flag
// ---------------------------------------------------------------------------
__device__ void producer_role(char* smem, const float* __restrict__ A,
                              const float* __restrict__ X, const float* __restrict__ W) {
    float* sW    = reinterpret_cast<float*>(smem);            // 32 KB [128][64]
    float* sred  = sW + DIN * DOUT;                           // 8 KB  [8][256]
    float* sX    = sred + 8 * 256;                            // 4 KB  [8][128]
    float* sdinv = sX + 8 * DIN;                              // 32 B  [8]
    const int tid = threadIdx.x;

    for (int i = tid; i < DIN * DOUT; i += 256) sW[i] = W[i];
    __syncthreads();

    for (int batch = blockIdx.x; batch < NN / 8; batch += NPROD) {
        const int base = batch * 8;

        // rowsum + convert 8 rows
        float part[8];
        #pragma unroll
        for (int rb = 0; rb < 8; rb++) {
            const int row = base + rb;
            const float4* a = reinterpret_cast<const float4*>(A + (size_t)row * NN);
            uint2* ah = reinterpret_cast<uint2*>(g_ah + (size_t)row * NN);
            float s = 0.f;
            #pragma unroll
            for (int j = 0; j < 8; j++) {
                float4 v = a[tid + 256 * j];
                s += (v.x + v.y) + (v.z + v.w);
                __half2 h01 = __floats2half2_rn(v.x, v.y);
                __half2 h23 = __floats2half2_rn(v.z, v.w);
                uint2 u;
                u.x = *reinterpret_cast<uint32_t*>(&h01);
                u.y = *reinterpret_cast<uint32_t*>(&h23);
                ah[tid + 256 * j] = u;
            }
            part[rb] = s;
        }
        #pragma unroll
        for (int rb = 0; rb < 8; rb++) sred[rb * 256 + tid] = part[rb];
        __syncthreads();

        // warp w reduces row w's 256 partials
        const int wid = tid >> 5, lane = tid & 31;
        if (wid < 8) {
            float s = 0.f;
            #pragma unroll
            for (int k = 0; k < 8; k++) s += sred[wid * 256 + lane + 32 * k];
            #pragma unroll
            for (int o = 16; o; o >>= 1) s += __shfl_xor_sync(0xFFFFFFFFu, s, o);
            if (lane == 0) {
                g_deg[base + wid] = s;
                sdinv[wid] = rsqrtf(s);
            }
        }
        __syncthreads();

        // sX = X rows scaled by dinv
        {
            const int xr = tid >> 5, xc = tid & 31;
            float4 xv = reinterpret_cast<const float4*>(X)[(size_t)(base + xr) * (DIN / 4) + xc];
            float dv = sdinv[xr];
            sX[xr * DIN + xc * 4 + 0] = xv.x * dv;
            sX[xr * DIN + xc * 4 + 1] = xv.y * dv;
            sX[xr * DIN + xc * 4 + 2] = xv.z * dv;
            sX[xr * DIN + xc * 4 + 3] = xv.w * dv;
        }
        __syncthreads();

        // Y rows: thread t -> row t>>5, col pair (t&31)*2 (f ascending, fp32 acc)
        {
            const int yr = tid >> 5, cp = (tid & 31) * 2;
            float y0 = 0.f, y1 = 0.f;
            #pragma unroll 8
            for (int f = 0; f < DIN; f++) {
                float xf = sX[yr * DIN + f];
                y0 += xf * sW[f * DOUT + cp];
                y1 += xf * sW[f * DOUT + cp + 1];
            }
            __half2 h = __floats2half2_rn(y0, y1);
            *reinterpret_cast<__half2*>(&g_yh[(size_t)(base + yr) * DOUT + cp]) = h;
        }

        __threadfence();
        __syncthreads();
        if (tid == 0) atomicAdd(&g_eighth[base >> 10], 8);
        __syncthreads();
    }
}

// ---------------------------------------------------------------------------
// Consumer: claim tiles ordered by w = max(s, m>>3); gate on BOTH eighth
// flags (s for Y rows + A k-slice, e = m>>3 for A_h M-rows); proven gemm body
// ---------------------------------------------------------------------------
__device__ __forceinline__ void load_chunk(uint32_t sbase, int stage, int c,
                                           const __half* __restrict__ Ablk,
                                           const __half* __restrict__ Bblk, int tid) {
    const uint32_t sA = sbase + (uint32_t)stage * A_STAGE_BYTES;
    const uint32_t sB = sbase + SMEM_B_BASE + (uint32_t)stage * B_STAGE_BYTES;
    const __half* ap = Ablk + (size_t)c * K_TILE;
    const __half* bp = Bblk + (size_t)c * K_TILE * DOUT;
    #pragma unroll
    for (int it = 0; it < 4; it++) {
        int idx = tid + 256 * it;
        int row = idx >> 3;
        int cc  = idx & 7;
        uint32_t dst = sA + (uint32_t)row * 128 + ((uint32_t)(cc ^ (row & 7)) << 4);
        CP_ASYNC16(dst, ap + (size_t)row * NN + cc * 8);
    }
    #pragma unroll
    for (int it = 0; it < 2; it++) {
        int idx = tid + 256 * it;
        int kr  = idx >> 3;
        int cc  = idx & 7;
        uint32_t dst = sB + (uint32_t)kr * 128 + ((uint32_t)(cc ^ (kr & 7)) << 4);
        CP_ASYNC16(dst, bp + (size_t)kr * DOUT + cc * 8);
    }
}

__device__ void consumer_role(char* smem) {
    const uint32_t sbase = smem_u32(smem);
    int* bc = reinterpret_cast<int*>(smem + SMEM_CTRL);
    const int tid  = threadIdx.x;
    const int lane = tid & 31;
    const int wid  = tid >> 5;
    const int wm   = wid & 3;
    const int wn   = wid >> 2;
    const int Ar0  = wm * 32;
    const int Cn0  = wn * 32;
    const int a_lrow = lane & 15;
    const int a_lk   = lane >> 4;
    const int b_lk   = lane & 15;
    const int b_ln8  = lane >> 4;

    for (;;) {
        if (tid == 0) *bc = atomicAdd(&g_ctask, 1);
        __syncthreads();                      // broadcast + separate prev tile's smem use
        const int t = *bc;
        __syncthreads();
        if (t >= NTILES) return;

        // tile enumeration ordered by w = max(s, e): unlocks as producer streams
        const int u = t >> 3;                 // dependency-pair index 0..63
        const int rr = t & 7;                 // m-tile within eighth e
        int w = 0;
        while ((w + 1) * (w + 1) <= u) w++;   // w = floor(sqrt(u)), u<64 -> <=8 iters
        const int j = u - w * w;              // 0..2w
        const int s = (j < w) ? j : w;        // k-split eighth
        const int e = (j < w) ? w : (j - w);  // A_h row eighth
        const int m = e * 8 + rr;             // m-tile 0..63

        if (tid == 0) {
            while (*(volatile int*)&g_eighth[s] < 1024 ||
                   *(volatile int*)&g_eighth[e] < 1024) __nanosleep(128);
        }
        __syncthreads();
        __threadfence();                      // order flag read before data reads

        const __half* Ablk = g_ah + (size_t)m * M_TILE * NN + (size_t)s * KPER;
        const __half* Bblk = g_yh + (size_t)s * KPER * DOUT;

        float acc[2][4][4];
        #pragma unroll
        for (int mi = 0; mi < 2; mi++)
            #pragma unroll
            for (int ni = 0; ni < 4; ni++)
                #pragma unroll
                for (int q = 0; q < 4; q++) acc[mi][ni][q] = 0.f;

        #pragma unroll
        for (int st = 0; st < STAGES - 1; st++) {
            load_chunk(sbase, st, st, Ablk, Bblk, tid);
            CP_COMMIT();
        }

        for (int c = 0; c < NCHUNK; c++) {
            CP_WAIT2();
            __syncthreads();

            const int st = c & (STAGES - 1);
            const uint32_t sA = sbase + (uint32_t)st * A_STAGE_BYTES;
            const uint32_t sB = sbase + SMEM_B_BASE + (uint32_t)st * B_STAGE_BYTES;

            if (c + STAGES - 1 < NCHUNK)
                load_chunk(sbase, (c + STAGES - 1) & (STAGES - 1), c + STAGES - 1, Ablk, Bblk, tid);
            CP_COMMIT();                      // commit EVERY iter (wait invariant)

            #pragma unroll
            for (int kk = 0; kk < K_TILE / 16; kk++) {
                uint32_t af[2][4];
                #pragma unroll
                for (int mi = 0; mi < 2; mi++) {
                    int r = Ar0 + mi * 16 + a_lrow;
                    ldsm_x4(af[mi], sA + (uint32_t)r * 128 +
                                    ((uint32_t)((kk * 2 + a_lk) ^ (r & 7)) << 4));
                }
                uint32_t bf[2][4];
                #pragma unroll
                for (int nb = 0; nb < 2; nb++) {
                    int kr = kk * 16 + b_lk;
                    int n  = Cn0 + nb * 16 + b_ln8 * 8;
                    ldsm_x4_t(bf[nb], sB + (uint32_t)kr * 128 +
                                      ((uint32_t)((n >> 3) ^ (kr & 7)) << 4));
                }
                #pragma unroll
                for (int mi = 0; mi < 2; mi++)
                    #pragma unroll
                    for (int ni = 0; ni < 4; ni++)
                        mma_f16(acc[mi][ni], af[mi],
                                bf[ni >> 1][2 * (ni & 1)], bf[ni >> 1][2 * (ni & 1) + 1]);
            }
        }

        // epilogue: acc -> g_hpart[s] as fp16
        __half* Hp = g_hpart[s];
        const int g = lane >> 2, q = lane & 3;
        const int R0 = m * M_TILE + wm * 32;
        #pragma unroll
        for (int mi = 0; mi < 2; mi++) {
            #pragma unroll
            for (int ni = 0; ni < 4; ni++) {
                int row = R0 + mi * 16 + g;
                int col = Cn0 + ni * 8 + q * 2;
                __half2 h0 = __floats2half2_rn(acc[mi][ni][0], acc[mi][ni][1]);
                __half2 h1 = __floats2half2_rn(acc[mi][ni][2], acc[mi][ni][3]);
                *reinterpret_cast<__half2*>(&Hp[(size_t)row * DOUT + col]) = h0;
                *reinterpret_cast<__half2*>(&Hp[(size_t)(row + 8) * DOUT + col]) = h1;
            }
        }
        __syncthreads();                      // tile done before smem reuse
    }
}

// ---------------------------------------------------------------------------
// Fused kernel: producers stream+convert A and build Y; consumers gemm
// ---------------------------------------------------------------------------
__global__ void __launch_bounds__(256, 2)
fused_kernel(const float* __restrict__ A, const float* __restrict__ X,
             const float* __restrict__ W) {
    extern __shared__ __align__(128) char smem[];
    if (blockIdx.x < NPROD) producer_role(smem, A, X, W);
    else                    consumer_role(smem);
}

// ---------------------------------------------------------------------------
// out_kernel: sum 8 fp16 partials, relu(d^-1/2 *), and reset sync state
// ---------------------------------------------------------------------------
__global__ void out_kernel(float* __restrict__ out) {
    if (blockIdx.x == 0 && threadIdx.x == 0) {
        g_ctask = 0;
        #pragma unroll
        for (int e = 0; e < SPLITK; e++) g_eighth[e] = 0;
    }
    int t = blockIdx.x * 256 + threadIdx.x;          // 65536 = NN*DOUT/8
    int row = t >> 3;
    int c8  = (t & 7) * 8;
    size_t o = (size_t)row * DOUT + c8;

    float r[8];
    #pragma unroll
    for (int i = 0; i < 8; i++) r[i] = 0.f;
    #pragma unroll
    for (int sp = 0; sp < SPLITK; sp++) {
        uint4 p = *reinterpret_cast<const uint4*>(&g_hpart[sp][o]);
        const uint32_t* u = &p.x;
        #pragma unroll
        for (int i = 0; i < 4; i++) {
            float2 v = __half22float2(*reinterpret_cast<const __half2*>(&u[i]));
            r[2 * i]     += v.x;
            r[2 * i + 1] += v.y;
        }
    }
    float s = rsqrtf(g_deg[row]);
    #pragma unroll
    for (int i = 0; i < 8; i++) r[i] = fmaxf(r[i] * s, 0.f);
    float4* op = reinterpret_cast<float4*>(&out[o]);
    op[0] = make_float4(r[0], r[1], r[2], r[3]);
    op[1] = make_float4(r[4], r[5], r[6], r[7]);
}

// ---------------------------------------------------------------------------
// Launch
// ---------------------------------------------------------------------------
extern "C" void kernel_launch(void* const* d_in, const int* in_sizes, int n_in,
                              void* d_out, int out_size) {
    const float* X = (const float*)d_in[0];   // features      [8192, 128]
    const float* A = (const float*)d_in[1];   // adjacency     [8192, 8192]
    const float* W = (const float*)d_in[2];   // weight        [128, 64]
    float* out = (float*)d_out;               // [8192, 64] fp32
    (void)in_sizes; (void)n_in; (void)out_size;

    static bool attr_set = false;
    if (!attr_set) {
        cudaFuncSetAttribute(fused_kernel, cudaFuncAttributeMaxDynamicSharedMemorySize, SMEM_TOTAL);
        attr_set = true;
    }

    fused_kernel<<<NGRID, 256, SMEM_TOTAL>>>(A, X, W);
    out_kernel<<<256, 256>>>(out);
}

// round 17
// speedup vs baseline: 1.2748x; 1.2748x over previous
#include <cuda_runtime.h>
#include <cuda_fp16.h>
#include <cstdint>

// Problem dims
#define NN   8192
#define DIN  128
#define DOUT 64

// One resident wave: 2 CTAs/SM x 148 SMs
#define NGRID  296

// Consumer gemm tiling (R5-proven skeleton, KPER = 1024)
#define M_TILE  128
#define K_TILE  64
#define SPLITK  8
#define KPER    (NN / SPLITK)      // 1024
#define NCHUNK  (KPER / K_TILE)    // 16
#define STAGES  4
#define NTILES  (SPLITK * (NN / M_TILE))   // 512

#define A_STAGE_BYTES (M_TILE * 128)            // 16 KB
#define B_STAGE_BYTES (K_TILE * 128)            // 8 KB
#define SMEM_B_BASE   (STAGES * A_STAGE_BYTES)  // 64 KB
#define SMEM_CTRL     (STAGES * (A_STAGE_BYTES + B_STAGE_BYTES))   // 96 KB
#define SMEM_TOTAL    (SMEM_CTRL + 16)          // + broadcast slot -> 2 CTAs/SM

// Scratch (no cudaMalloc allowed; zero-initialized)
__device__ __align__(16) float  g_deg[NN];
__device__ __align__(16) __half g_ah[(size_t)NN * NN];               // fp16 copy of A
__device__ __align__(16) __half g_yh[(size_t)NN * DOUT];             // Y = d^-1/2*(X@W), fp16
__device__ __align__(16) __half g_hpart[SPLITK][(size_t)NN * DOUT];  // split-K partials (fp16)
__device__ int g_eighth[SPLITK];   // rows completed per 1024-row eighth
__device__ int g_ctask;            // consumer tile queue head

// ---------------------------------------------------------------------------
// PTX helpers (generic PTX only — harness compiles through compute_103 base)
// ---------------------------------------------------------------------------
__device__ __forceinline__ uint32_t smem_u32(const void* p) {
    uint32_t a;
    asm("{ .reg .u64 t; cvta.to.shared.u64 t, %1; cvt.u32.u64 %0, t; }" : "=r"(a) : "l"(p));
    return a;
}

#define CP_ASYNC16(dst, src) \
    asm volatile("cp.async.cg.shared.global [%0], [%1], 16;" :: "r"(dst), "l"(src) : "memory")
#define CP_COMMIT() asm volatile("cp.async.commit_group;" ::: "memory")
#define CP_WAIT2()  asm volatile("cp.async.wait_group 2;" ::: "memory")

__device__ __forceinline__ void ldsm_x4(uint32_t r[4], uint32_t addr) {
    asm volatile("ldmatrix.sync.aligned.m8n8.x4.shared.b16 {%0,%1,%2,%3}, [%4];"
                 : "=r"(r[0]), "=r"(r[1]), "=r"(r[2]), "=r"(r[3]) : "r"(addr));
}
__device__ __forceinline__ void ldsm_x4_t(uint32_t r[4], uint32_t addr) {
    asm volatile("ldmatrix.sync.aligned.m8n8.x4.trans.shared.b16 {%0,%1,%2,%3}, [%4];"
                 : "=r"(r[0]), "=r"(r[1]), "=r"(r[2]), "=r"(r[3]) : "r"(addr));
}
__device__ __forceinline__ void mma_f16(float c[4], const uint32_t a[4], uint32_t b0, uint32_t b1) {
    asm volatile(
        "mma.sync.aligned.m16n8k16.row.col.f32.f16.f16.f32 "
        "{%0,%1,%2,%3}, {%4,%5,%6,%7}, {%8,%9}, {%0,%1,%2,%3};"
        : "+f"(c[0]), "+f"(c[1]), "+f"(c[2]), "+f"(c[3])
        : "r"(a[0]), "r"(a[1]), "r"(a[2]), "r"(a[3]), "r"(b0), "r"(b1));
}

// ---------------------------------------------------------------------------
// Producer phase (run by ALL CTAs): 8-row batches — rowsum + fp16 convert +
// Y rows; bump eighth flag. Same per-thread A partial order as the proven
// rowsum_convert kernel.
// ---------------------------------------------------------------------------
__device__ void produce_all(char* smem, const float* __restrict__ A,
                            const float* __restrict__ X, const float* __restrict__ W) {
    float* sW    = reinterpret_cast<float*>(smem);            // 32 KB [128][64]
    float* sred  = sW + DIN * DOUT;                           // 8 KB  [8][256]
    float* sX    = sred + 8 * 256;                            // 4 KB  [8][128]
    float* sdinv = sX + 8 * DIN;                              // 32 B  [8]
    const int tid = threadIdx.x;

    for (int i = tid; i < DIN * DOUT; i += 256) sW[i] = W[i];
    __syncthreads();

    for (int batch = blockIdx.x; batch < NN / 8; batch += NGRID) {
        const int base = batch * 8;

        // rowsum + convert 8 rows
        float part[8];
        #pragma unroll
        for (int rb = 0; rb < 8; rb++) {
            const int row = base + rb;
            const float4* a = reinterpret_cast<const float4*>(A + (size_t)row * NN);
            uint2* ah = reinterpret_cast<uint2*>(g_ah + (size_t)row * NN);
            float s = 0.f;
            #pragma unroll
            for (int j = 0; j < 8; j++) {
                float4 v = a[tid + 256 * j];
                s += (v.x + v.y) + (v.z + v.w);
                __half2 h01 = __floats2half2_rn(v.x, v.y);
                __half2 h23 = __floats2half2_rn(v.z, v.w);
                uint2 u;
                u.x = *reinterpret_cast<uint32_t*>(&h01);
                u.y = *reinterpret_cast<uint32_t*>(&h23);
                ah[tid + 256 * j] = u;
            }
            part[rb] = s;
        }
        #pragma unroll
        for (int rb = 0; rb < 8; rb++) sred[rb * 256 + tid] = part[rb];
        __syncthreads();

        // warp w reduces row w's 256 partials
        const int wid = tid >> 5, lane = tid & 31;
        if (wid < 8) {
            float s = 0.f;
            #pragma unroll
            for (int k = 0; k < 8; k++) s += sred[wid * 256 + lane + 32 * k];
            #pragma unroll
            for (int o = 16; o; o >>= 1) s += __shfl_xor_sync(0xFFFFFFFFu, s, o);
            if (lane == 0) {
                g_deg[base + wid] = s;
                sdinv[wid] = rsqrtf(s);
            }
        }
        __syncthreads();

        // sX = X rows scaled by dinv
        {
            const int xr = tid >> 5, xc = tid & 31;
            float4 xv = reinterpret_cast<const float4*>(X)[(size_t)(base + xr) * (DIN / 4) + xc];
            float dv = sdinv[xr];
            sX[xr * DIN + xc * 4 + 0] = xv.x * dv;
            sX[xr * DIN + xc * 4 + 1] = xv.y * dv;
            sX[xr * DIN + xc * 4 + 2] = xv.z * dv;
            sX[xr * DIN + xc * 4 + 3] = xv.w * dv;
        }
        __syncthreads();

        // Y rows: thread t -> row t>>5, col pair (t&31)*2 (f ascending, fp32 acc)
        {
            const int yr = tid >> 5, cp = (tid & 31) * 2;
            float y0 = 0.f, y1 = 0.f;
            #pragma unroll 8
            for (int f = 0; f < DIN; f++) {
                float xf = sX[yr * DIN + f];
                y0 += xf * sW[f * DOUT + cp];
                y1 += xf * sW[f * DOUT + cp + 1];
            }
            __half2 h = __floats2half2_rn(y0, y1);
            *reinterpret_cast<__half2*>(&g_yh[(size_t)(base + yr) * DOUT + cp]) = h;
        }

        __threadfence();
        __syncthreads();
        if (tid == 0) atomicAdd(&g_eighth[base >> 10], 8);
        __syncthreads();
    }
}

// ---------------------------------------------------------------------------
// Consumer phase (run by ALL CTAs after their production share):
// claim tiles ordered by w = max(s, e); gate on BOTH eighth flags
// ---------------------------------------------------------------------------
__device__ __forceinline__ void load_chunk(uint32_t sbase, int stage, int c,
                                           const __half* __restrict__ Ablk,
                                           const __half* __restrict__ Bblk, int tid) {
    const uint32_t sA = sbase + (uint32_t)stage * A_STAGE_BYTES;
    const uint32_t sB = sbase + SMEM_B_BASE + (uint32_t)stage * B_STAGE_BYTES;
    const __half* ap = Ablk + (size_t)c * K_TILE;
    const __half* bp = Bblk + (size_t)c * K_TILE * DOUT;
    #pragma unroll
    for (int it = 0; it < 4; it++) {
        int idx = tid + 256 * it;
        int row = idx >> 3;
        int cc  = idx & 7;
        uint32_t dst = sA + (uint32_t)row * 128 + ((uint32_t)(cc ^ (row & 7)) << 4);
        CP_ASYNC16(dst, ap + (size_t)row * NN + cc * 8);
    }
    #pragma unroll
    for (int it = 0; it < 2; it++) {
        int idx = tid + 256 * it;
        int kr  = idx >> 3;
        int cc  = idx & 7;
        uint32_t dst = sB + (uint32_t)kr * 128 + ((uint32_t)(cc ^ (kr & 7)) << 4);
        CP_ASYNC16(dst, bp + (size_t)kr * DOUT + cc * 8);
    }
}

__device__ void consume_all(char* smem) {
    const uint32_t sbase = smem_u32(smem);
    int* bc = reinterpret_cast<int*>(smem + SMEM_CTRL);
    const int tid  = threadIdx.x;
    const int lane = tid & 31;
    const int wid  = tid >> 5;
    const int wm   = wid & 3;
    const int wn   = wid >> 2;
    const int Ar0  = wm * 32;
    const int Cn0  = wn * 32;
    const int a_lrow = lane & 15;
    const int a_lk   = lane >> 4;
    const int b_lk   = lane & 15;
    const int b_ln8  = lane >> 4;

    for (;;) {
        if (tid == 0) *bc = atomicAdd(&g_ctask, 1);
        __syncthreads();
        const int t = *bc;
        __syncthreads();
        if (t >= NTILES) return;

        // tile enumeration ordered by w = max(s, e): unlocks as production proceeds
        const int u = t >> 3;                 // dependency-pair index 0..63
        const int rr = t & 7;                 // m-tile within eighth e
        int w = 0;
        while ((w + 1) * (w + 1) <= u) w++;   // w = floor(sqrt(u))
        const int j = u - w * w;              // 0..2w
        const int s = (j < w) ? j : w;        // k-split eighth
        const int e = (j < w) ? w : (j - w);  // A_h row eighth
        const int m = e * 8 + rr;             // m-tile 0..63

        if (tid == 0) {
            while (*(volatile int*)&g_eighth[s] < 1024 ||
                   *(volatile int*)&g_eighth[e] < 1024) __nanosleep(128);
        }
        __syncthreads();
        __threadfence();

        const __half* Ablk = g_ah + (size_t)m * M_TILE * NN + (size_t)s * KPER;
        const __half* Bblk = g_yh + (size_t)s * KPER * DOUT;

        float acc[2][4][4];
        #pragma unroll
        for (int mi = 0; mi < 2; mi++)
            #pragma unroll
            for (int ni = 0; ni < 4; ni++)
                #pragma unroll
                for (int q = 0; q < 4; q++) acc[mi][ni][q] = 0.f;

        #pragma unroll
        for (int st = 0; st < STAGES - 1; st++) {
            load_chunk(sbase, st, st, Ablk, Bblk, tid);
            CP_COMMIT();
        }

        for (int c = 0; c < NCHUNK; c++) {
            CP_WAIT2();
            __syncthreads();

            const int st = c & (STAGES - 1);
            const uint32_t sA = sbase + (uint32_t)st * A_STAGE_BYTES;
            const uint32_t sB = sbase + SMEM_B_BASE + (uint32_t)st * B_STAGE_BYTES;

            if (c + STAGES - 1 < NCHUNK)
                load_chunk(sbase, (c + STAGES - 1) & (STAGES - 1), c + STAGES - 1, Ablk, Bblk, tid);
            CP_COMMIT();                      // commit EVERY iter (wait invariant)

            #pragma unroll
            for (int kk = 0; kk < K_TILE / 16; kk++) {
                uint32_t af[2][4];
                #pragma unroll
                for (int mi = 0; mi < 2; mi++) {
                    int r = Ar0 + mi * 16 + a_lrow;
                    ldsm_x4(af[mi], sA + (uint32_t)r * 128 +
                                    ((uint32_t)((kk * 2 + a_lk) ^ (r & 7)) << 4));
                }
                uint32_t bf[2][4];
                #pragma unroll
                for (int nb = 0; nb < 2; nb++) {
                    int kr = kk * 16 + b_lk;
                    int n  = Cn0 + nb * 16 + b_ln8 * 8;
                    ldsm_x4_t(bf[nb], sB + (uint32_t)kr * 128 +
                                      ((uint32_t)((n >> 3) ^ (kr & 7)) << 4));
                }
                #pragma unroll
                for (int mi = 0; mi < 2; mi++)
                    #pragma unroll
                    for (int ni = 0; ni < 4; ni++)
                        mma_f16(acc[mi][ni], af[mi],
                                bf[ni >> 1][2 * (ni & 1)], bf[ni >> 1][2 * (ni & 1) + 1]);
            }
        }

        // epilogue: acc -> g_hpart[s] as fp16
        __half* Hp = g_hpart[s];
        const int g = lane >> 2, q = lane & 3;
        const int R0 = m * M_TILE + wm * 32;
        #pragma unroll
        for (int mi = 0; mi < 2; mi++) {
            #pragma unroll
            for (int ni = 0; ni < 4; ni++) {
                int row = R0 + mi * 16 + g;
                int col = Cn0 + ni * 8 + q * 2;
                __half2 h0 = __floats2half2_rn(acc[mi][ni][0], acc[mi][ni][1]);
                __half2 h1 = __floats2half2_rn(acc[mi][ni][2], acc[mi][ni][3]);
                *reinterpret_cast<__half2*>(&Hp[(size_t)row * DOUT + col]) = h0;
                *reinterpret_cast<__half2*>(&Hp[(size_t)(row + 8) * DOUT + col]) = h1;
            }
        }
        __syncthreads();
    }
}

// ---------------------------------------------------------------------------
// Fused kernel: every CTA produces its share, then consumes gated tiles
// ---------------------------------------------------------------------------
__global__ void __launch_bounds__(256, 2)
fused_kernel(const float* __restrict__ A, const float* __restrict__ X,
             const float* __restrict__ W) {
    extern __shared__ __align__(128) char smem[];
    produce_all(smem, A, X, W);
    consume_all(smem);
}

// ---------------------------------------------------------------------------
// out_kernel: sum 8 fp16 partials, relu(d^-1/2 *), and reset sync state
// ---------------------------------------------------------------------------
__global__ void out_kernel(float* __restrict__ out) {
    if (blockIdx.x == 0 && threadIdx.x == 0) {
        g_ctask = 0;
        #pragma unroll
        for (int e = 0; e < SPLITK; e++) g_eighth[e] = 0;
    }
    int t = blockIdx.x * 256 + threadIdx.x;          // 65536 = NN*DOUT/8
    int row = t >> 3;
    int c8  = (t & 7) * 8;
    size_t o = (size_t)row * DOUT + c8;

    float r[8];
    #pragma unroll
    for (int i = 0; i < 8; i++) r[i] = 0.f;
    #pragma unroll
    for (int sp = 0; sp < SPLITK; sp++) {
        uint4 p = *reinterpret_cast<const uint4*>(&g_hpart[sp][o]);
        const uint32_t* u = &p.x;
        #pragma unroll
        for (int i = 0; i < 4; i++) {
            float2 v = __half22float2(*reinterpret_cast<const __half2*>(&u[i]));
            r[2 * i]     += v.x;
            r[2 * i + 1] += v.y;
        }
    }
    float s = rsqrtf(g_deg[row]);
    #pragma unroll
    for (int i = 0; i < 8; i++) r[i] = fmaxf(r[i] * s, 0.f);
    float4* op = reinterpret_cast<float4*>(&out[o]);
    op[0] = make_float4(r[0], r[1], r[2], r[3]);
    op[1] = make_float4(r[4], r[5], r[6], r[7]);
}

// ---------------------------------------------------------------------------
// Launch
// ---------------------------------------------------------------------------
extern "C" void kernel_launch(void* const* d_in, const int* in_sizes, int n_in,
                              void* d_out, int out_size) {
    const float* X = (const float*)d_in[0];   // features      [8192, 128]
    const float* A = (const float*)d_in[1];   // adjacency     [8192, 8192]
    const float* W = (const float*)d_in[2];   // weight        [128, 64]
    float* out = (float*)d_out;               // [8192, 64] fp32
    (void)in_sizes; (void)n_in; (void)out_size;

    static bool attr_set = false;
    if (!attr_set) {
        cudaFuncSetAttribute(fused_kernel, cudaFuncAttributeMaxDynamicSharedMemorySize, SMEM_TOTAL);
        attr_set = true;
    }

    fused_kernel<<<NGRID, 256, SMEM_TOTAL>>>(A, X, W);
    out_kernel<<<256, 256>>>(out);
}